// round 6
// baseline (speedup 1.0000x reference)
#include <cuda_runtime.h>
#include <cuda_bf16.h>
#include <cstdint>

#define S_LEN  512
#define BATCH  64
#define HID    1024
#define LAYERS 3
#define BH     (BATCH*HID)     // 65536
#define NTILE  32              // unit tiles per layer (32 hidden units each)
#define BROWS  192             // weight rows per tile: 96 Wih + 96 Whh
#define KCH    64              // K per chunk (s8: 64 bytes/row)
#define CHUNKS 16              // 1024 / 64
#define DEPTH  4               // cp.async ring depth

#define ROWB   80              // smem row stride bytes (64 used + 16 pad)
// slot rows: [0,64)Ax_d1 [64,128)Ax_d2 [128,192)Ah_d1 [192,256)Ah_d2
//            [256,352)Wih_d1 [352,448)Wih_d2 [448,544)Whh_d1 [544,640)Whh_d2
#define SLOT_BYTES (640*ROWB)            // 51200
#define SMEM_REQ (1024 + DEPTH*SLOT_BYTES)   // 205824 B

typedef __nv_bfloat16 bf16;

// ---------------- device scratch (no runtime allocation) -------------------
__device__ __align__(16) char g_xd1[(size_t)S_LEN*BH];
__device__ __align__(16) char g_xd2[(size_t)S_LEN*BH];
__device__ __align__(16) char g_wd1[(size_t)LAYERS*NTILE*BROWS*HID];  // tile-contig
__device__ __align__(16) char g_wd2[(size_t)LAYERS*NTILE*BROWS*HID];
__device__ float g_h[LAYERS*2*BH];            // fp32 h, parity double buffer
__device__ __align__(16) char g_hd1[LAYERS*2*BH];
__device__ __align__(16) char g_hd2[LAYERS*2*BH];
__device__ float g_S[8];   // [0]=Sx [1]=Sh0 [2+l]=Swih_l [5+l]=Swhh_l

// ---------------- helpers ----------------------------------------------------
__device__ __forceinline__ void ldsm4(uint32_t r[4], const void* p) {
    uint32_t a = (uint32_t)__cvta_generic_to_shared(p);
    asm volatile("ldmatrix.sync.aligned.m8n8.x4.shared.b16 {%0,%1,%2,%3}, [%4];"
                 : "=r"(r[0]), "=r"(r[1]), "=r"(r[2]), "=r"(r[3]) : "r"(a));
}

__device__ __forceinline__ void imma16832(int c[4], const uint32_t a[4],
                                          uint32_t b0, uint32_t b1) {
    asm volatile("mma.sync.aligned.m16n8k32.row.col.s32.s8.s8.s32 "
                 "{%0,%1,%2,%3}, {%4,%5,%6,%7}, {%8,%9}, {%0,%1,%2,%3};"
                 : "+r"(c[0]), "+r"(c[1]), "+r"(c[2]), "+r"(c[3])
                 : "r"(a[0]), "r"(a[1]), "r"(a[2]), "r"(a[3]), "r"(b0), "r"(b1));
}

__device__ __forceinline__ void cp16(void* dst, const void* src) {
    uint32_t d = (uint32_t)__cvta_generic_to_shared(dst);
    asm volatile("cp.async.cg.shared.global [%0], [%1], 16;" :: "r"(d), "l"(src));
}

// digit split: u = v*(127/S); d1 = rint(u) in [-127,127]; d2 = rint((u-d1)*128)
__device__ __forceinline__ void quant2(float v, float inv127S, char& d1, char& d2) {
    float u  = v * inv127S;
    float q1 = rintf(u);
    d1 = (char)(int)q1;
    d2 = (char)(int)rintf((u - q1) * 128.f);
}

// ---------------- prep kernels ----------------------------------------------
__global__ void init_scales_kernel() {
    if (threadIdx.x < 8) g_S[threadIdx.x] = 0.f;
}

__global__ void absmax_kernel(const float* __restrict__ p, size_t n, int dst) {
    float m = 0.f;
    for (size_t i = (size_t)blockIdx.x * blockDim.x + threadIdx.x; i < n;
         i += (size_t)gridDim.x * blockDim.x)
        m = fmaxf(m, fabsf(p[i]));
#pragma unroll
    for (int o = 16; o; o >>= 1) m = fmaxf(m, __shfl_xor_sync(~0u, m, o));
    __shared__ float sm[32];
    if ((threadIdx.x & 31) == 0) sm[threadIdx.x >> 5] = m;
    __syncthreads();
    if (threadIdx.x < 32) {
        m = (threadIdx.x < (blockDim.x >> 5)) ? sm[threadIdx.x] : 0.f;
#pragma unroll
        for (int o = 16; o; o >>= 1) m = fmaxf(m, __shfl_xor_sync(~0u, m, o));
        if (threadIdx.x == 0) atomicMax((int*)&g_S[dst], __float_as_int(m));
    }
}

__global__ void quant_w_kernel(const float* __restrict__ wih,
                               const float* __restrict__ whh) {
    size_t i = (size_t)blockIdx.x * blockDim.x + threadIdx.x;
    if (i >= (size_t)LAYERS * 3 * HID * HID) return;
    int k = (int)(i % HID);
    size_t row = i / HID;
    int l = (int)(row / (3 * HID));
    int r = (int)(row % (3 * HID));
    int g = r >> 10, u = r & 1023;
    int tile = u >> 5, uu = u & 31;
    size_t dih = (((size_t)(l * NTILE + tile)) * BROWS + g * 32 + uu) * HID + k;
    size_t dhh = dih + (size_t)96 * HID;
    float invI = 127.f / fmaxf(g_S[2 + l], 1e-20f);
    float invH = 127.f / fmaxf(g_S[5 + l], 1e-20f);
    char d1, d2;
    quant2(wih[i], invI, d1, d2); g_wd1[dih] = d1; g_wd2[dih] = d2;
    quant2(whh[i], invH, d1, d2); g_wd1[dhh] = d1; g_wd2[dhh] = d2;
}

__global__ void quant_x_kernel(const float* __restrict__ x) {
    size_t i = (size_t)blockIdx.x * blockDim.x + threadIdx.x;
    if (i >= (size_t)S_LEN * BH) return;
    float inv = 127.f / fmaxf(g_S[0], 1e-20f);
    char d1, d2;
    quant2(x[i], inv, d1, d2);
    g_xd1[i] = d1; g_xd2[i] = d2;
}

__global__ void init_h_kernel(const float* __restrict__ h0) {
    size_t i = (size_t)blockIdx.x * blockDim.x + threadIdx.x;
    if (i >= (size_t)LAYERS * BH) return;
    int l = (int)(i / BH);
    size_t j = i % BH;
    float v = h0[i];
    size_t dst = ((size_t)l * 2 + 0) * BH + j;
    g_h[dst] = v;
    float inv = 127.f / fmaxf(g_S[1], 1.f);
    char d1, d2;
    quant2(v, inv, d1, d2);
    g_hd1[dst] = d1; g_hd2[dst] = d2;
}

// ---------------- chunk loader ------------------------------------------------
__device__ __forceinline__ void load_chunk(
    char* slot, int kb,
    const char* __restrict__ Ax1, const char* __restrict__ Ax2,
    const char* __restrict__ Ah1, const char* __restrict__ Ah2,
    const char* __restrict__ W1,  const char* __restrict__ W2,  // 192 x 1024 tile
    int tid)
{
    // A: 4 regions x 64 rows x 64 B  (4 x 16B per row)
#pragma unroll
    for (int i = tid; i < 1024; i += 512) {
        int row = i >> 2, c16 = i & 3;
        int reg = row >> 6, r = row & 63;
        const char* src = (reg == 0) ? Ax1 : (reg == 1) ? Ax2 : (reg == 2) ? Ah1 : Ah2;
        cp16(slot + row * ROWB + c16 * 16, src + (size_t)r * HID + kb + c16 * 16);
    }
    // W: 4 regions x 96 rows x 64 B
#pragma unroll
    for (int i = tid; i < 1536; i += 512) {
        int row = i >> 2, c16 = i & 3;
        int reg = row / 96, r = row - reg * 96;
        const char* src = (reg & 1) ? W2 : W1;
        size_t grow = (size_t)((reg >> 1) * 96 + r) * HID + kb + c16 * 16;
        cp16(slot + (256 + row) * ROWB + c16 * 16, src + grow);
    }
}

// ---------------- fused GRU step (int8 digit IMMA, layer wavefront) --------
// grid (32, LAYERS), 512 threads = 16 warps: wp(path) x 4 wm x 2 wn.
__global__ __launch_bounds__(512) void gru_step_kernel(
    int gs, const float* __restrict__ bih, const float* __restrict__ bhh,
    float* __restrict__ out)
{
    const int l = blockIdx.y;
    const int t = gs - l;
    if (t < 0 || t >= S_LEN) return;

    const int tile = blockIdx.x;
    const int u0   = tile * 32;
    const int tid  = threadIdx.x;
    const int lane = tid & 31;
    const int wid  = tid >> 5;
    const int wp   = wid >> 3;          // 0: x-path (gi), 1: h-path (gh)
    const int wm   = (wid >> 1) & 3;    // batch rows 16*wm
    const int wn   = wid & 1;           // gate cols 48*wn

    extern __shared__ __align__(16) unsigned char smem_raw[];
    uint32_t dyn_u = (uint32_t)__cvta_generic_to_shared(smem_raw);
    uint32_t s0u   = (dyn_u + 1023u) & ~1023u;
    char* sbase = (char*)smem_raw + (s0u - dyn_u);

    const int par = t & 1;
    const char *Ax1, *Ax2;
    if (l == 0) {
        Ax1 = g_xd1 + (size_t)t * BH;  Ax2 = g_xd2 + (size_t)t * BH;
    } else {
        size_t o = ((size_t)(l - 1) * 2 + (par ^ 1)) * BH;   // h_{l-1}[t]
        Ax1 = g_hd1 + o;  Ax2 = g_hd2 + o;
    }
    size_t oh = ((size_t)l * 2 + par) * BH;                   // h_l[t-1]
    const char* Ah1 = g_hd1 + oh;
    const char* Ah2 = g_hd2 + oh;
    size_t ob = ((size_t)(l * NTILE + tile)) * BROWS * HID;
    const char* W1 = g_wd1 + ob;
    const char* W2 = g_wd2 + ob;

    int accA[6][4], accB[6][4];
#pragma unroll
    for (int j = 0; j < 6; ++j)
#pragma unroll
        for (int q = 0; q < 4; ++q) { accA[j][q] = 0; accB[j][q] = 0; }

    // fragment addressing
    const int aB1 = wp * 128;                  // A d1 rows; d2 = +64
    const int wB1 = 256 + wp * 192;            // W d1 rows; d2 = +96
    const int rA  = wm * 16 + (lane & 15);
    const int rW  = wn * 48 + (lane & 15);
    const int h16 = (lane >> 4) * 16;          // byte offset for k-half tiles

    // ---- prologue: prefetch chunks 0..2 ----
#pragma unroll
    for (int c = 0; c < DEPTH - 1; ++c) {
        load_chunk(sbase + (size_t)c * SLOT_BYTES, c * KCH,
                   Ax1, Ax2, Ah1, Ah2, W1, W2, tid);
        asm volatile("cp.async.commit_group;" ::: "memory");
    }

    // ---- main loop: 16 chunks (K=64), depth-4 ring ----
    for (int c = 0; c < CHUNKS; ++c) {
        asm volatile("cp.async.wait_group 2;" ::: "memory");
        __syncthreads();
        const int nc = c + DEPTH - 1;
        if (nc < CHUNKS)
            load_chunk(sbase + (size_t)(nc & (DEPTH - 1)) * SLOT_BYTES, nc * KCH,
                       Ax1, Ax2, Ah1, Ah2, W1, W2, tid);
        asm volatile("cp.async.commit_group;" ::: "memory");   // drain-safe

        char* slot = sbase + (size_t)(c & (DEPTH - 1)) * SLOT_BYTES;
#pragma unroll
        for (int s = 0; s < 2; ++s) {                          // 2 x k32
            uint32_t a1[4], a2[4];
            ldsm4(a1, slot + (aB1 +      rA) * ROWB + s * 32 + h16);
            ldsm4(a2, slot + (aB1 + 64 + rA) * ROWB + s * 32 + h16);
#pragma unroll
            for (int m = 0; m < 3; ++m) {
                uint32_t w1[4], w2[4];
                char* wptr = slot + (wB1 + rW + m * 16) * ROWB + s * 32 + h16;
                ldsm4(w1, wptr);
                ldsm4(w2, wptr + 96 * ROWB);
                // d1*d1 -> accA ; d1*d2 + d2*d1 -> accB
                imma16832(accA[2 * m],     a1, w1[0], w1[2]);
                imma16832(accB[2 * m],     a1, w2[0], w2[2]);
                imma16832(accB[2 * m],     a2, w1[0], w1[2]);
                imma16832(accA[2 * m + 1], a1, w1[1], w1[3]);
                imma16832(accB[2 * m + 1], a1, w2[1], w2[3]);
                imma16832(accB[2 * m + 1], a2, w1[1], w1[3]);
            }
        }
    }
    asm volatile("cp.async.wait_group 0;" ::: "memory");
    __syncthreads();

    // ---- epilogue: dequant accumulators -> smem gi/gh ---------------------
    float* sGI = (float*)sbase;          // 64 x 96
    float* sGH = sGI + 64 * 96;          // 64 x 96
    {
        float S1 = fmaxf(g_S[1], 1.f);
        float SA = wp ? S1 : (l == 0 ? fmaxf(g_S[0], 1e-20f) : S1);
        float SW = fmaxf(wp ? g_S[5 + l] : g_S[2 + l], 1e-20f);
        float F  = SA * SW * (1.f / 16129.f);    // /127^2
        float* dstbuf = wp ? sGH : sGI;
        int g  = lane >> 2;
        int t4 = lane & 3;
#pragma unroll
        for (int j = 0; j < 6; ++j) {
            int col = wn * 48 + j * 8 + t4 * 2;
            int r0  = wm * 16 + g;
            dstbuf[r0 * 96 + col] =
                F * ((float)accA[j][0] + (float)accB[j][0] * 0.0078125f);
            dstbuf[r0 * 96 + col + 1] =
                F * ((float)accA[j][1] + (float)accB[j][1] * 0.0078125f);
            dstbuf[(r0 + 8) * 96 + col] =
                F * ((float)accA[j][2] + (float)accB[j][2] * 0.0078125f);
            dstbuf[(r0 + 8) * 96 + col + 1] =
                F * ((float)accA[j][3] + (float)accB[j][3] * 0.0078125f);
        }
    }
    __syncthreads();

    const int lG = l * 3 * HID;
    const float* bihp = bih + lG;
    const float* bhhp = bhh + lG;
    const float* hsrc = g_h + ((size_t)l * 2 + par) * BH;
    float*       hdst = g_h + ((size_t)l * 2 + (par ^ 1)) * BH;
    char* hd1 = g_hd1 + ((size_t)l * 2 + (par ^ 1)) * BH;
    char* hd2 = g_hd2 + ((size_t)l * 2 + (par ^ 1)) * BH;
    const float ShInv = 127.f / fmaxf(g_S[1], 1.f);

#pragma unroll
    for (int it = 0; it < 4; ++it) {
        int idx = it * 512 + tid;
        int b = idx >> 5, u = idx & 31;
        int ug = u0 + u;
        float gi_r = sGI[b * 96 + u],       gh_r = sGH[b * 96 + u];
        float gi_z = sGI[b * 96 + 32 + u],  gh_z = sGH[b * 96 + 32 + u];
        float gi_n = sGI[b * 96 + 64 + u],  gh_n = sGH[b * 96 + 64 + u];
        float pr = gi_r + bihp[ug]           + gh_r + bhhp[ug];
        float pz = gi_z + bihp[HID + ug]     + gh_z + bhhp[HID + ug];
        float rg = 1.f / (1.f + __expf(-pr));
        float zg = 1.f / (1.f + __expf(-pz));
        float nn = tanhf(gi_n + bihp[2 * HID + ug] + rg * (gh_n + bhhp[2 * HID + ug]));
        float hold = hsrc[(size_t)b * HID + ug];
        float hn = (1.f - zg) * nn + zg * hold;   // |hn| <= max(1,|hold|) <= Sh
        hdst[(size_t)b * HID + ug] = hn;
        char d1, d2;
        quant2(hn, ShInv, d1, d2);
        hd1[(size_t)b * HID + ug] = d1;
        hd2[(size_t)b * HID + ug] = d2;
        if (l == LAYERS - 1)
            out[(size_t)t * BH + (size_t)b * HID + ug] = hn;
    }
}

// ---------------- launch -----------------------------------------------------
extern "C" void kernel_launch(void* const* d_in, const int* in_sizes, int n_in,
                              void* d_out, int out_size)
{
    const float* x   = (const float*)d_in[0];
    const float* h0  = (const float*)d_in[1];
    const float* wih = (const float*)d_in[2];
    const float* whh = (const float*)d_in[3];
    const float* bih = (const float*)d_in[4];
    const float* bhh = (const float*)d_in[5];
    float* out = (float*)d_out;

    cudaFuncSetAttribute(gru_step_kernel,
                         cudaFuncAttributeMaxDynamicSharedMemorySize, SMEM_REQ);

    init_scales_kernel<<<1, 32>>>();
    absmax_kernel<<<2048, 256>>>(x,  (size_t)S_LEN * BH, 0);
    absmax_kernel<<<256, 256>>>(h0, (size_t)LAYERS * BH, 1);
    for (int l = 0; l < LAYERS; ++l) {
        size_t off = (size_t)l * 3 * HID * HID;
        absmax_kernel<<<512, 256>>>(wih + off, (size_t)3 * HID * HID, 2 + l);
        absmax_kernel<<<512, 256>>>(whh + off, (size_t)3 * HID * HID, 5 + l);
    }
    {
        size_t n = (size_t)LAYERS * 3 * HID * HID;
        quant_w_kernel<<<(unsigned)((n + 255) / 256), 256>>>(wih, whh);
    }
    {
        size_t n = (size_t)S_LEN * BH;
        quant_x_kernel<<<(unsigned)((n + 255) / 256), 256>>>(x);
    }
    {
        size_t n = (size_t)LAYERS * BH;
        init_h_kernel<<<(unsigned)((n + 255) / 256), 256>>>(h0);
    }
    for (int gs = 0; gs < S_LEN + LAYERS - 1; ++gs)
        gru_step_kernel<<<dim3(NTILE, LAYERS), 512, SMEM_REQ>>>(gs, bih, bhh, out);
}

// round 7
// speedup vs baseline: 2.9005x; 2.9005x over previous
#include <cuda_runtime.h>
#include <cuda_bf16.h>
#include <cstdint>

#define S_LEN  512
#define BATCH  64
#define HID    1024
#define LAYERS 3
#define BH     (BATCH*HID)     // 65536
#define KCH    64              // K per chunk
#define CHUNKS 16              // 1024/64
#define DEPTH  3               // cp.async ring depth

#define SR     72              // smem row stride in halfs (144B; ldsm conflict-free)
// slot rows: [0,64) A_hi, [64,128) A_lo, [128,256) W_hi, [256,384) W_lo
#define SLOT_HALFS (384*SR)            // 27648
#define SLOT_BYTES (SLOT_HALFS*2)      // 55296
#define SMEM_REQ (1024 + DEPTH*SLOT_BYTES)   // 166912 B

#define WBLK   (128*1024)      // one weight block: 128 rows x K=1024

typedef __nv_bfloat16 bf16;

// ---------------- device scratch (no runtime allocation) -------------------
__device__ bf16 g_xhi[(size_t)S_LEN*BH];
__device__ bf16 g_xlo[(size_t)S_LEN*BH];
// weight blocks: [l][p][g][ub] each 128x1024, hi/lo planes
__device__ bf16 g_wBhi[(size_t)LAYERS*2*3*8*WBLK];
__device__ bf16 g_wBlo[(size_t)LAYERS*2*3*8*WBLK];
__device__ float g_h  [LAYERS*2*BH];          // fp32 h, parity double buffer
__device__ bf16  g_hhi[LAYERS*2*BH];
__device__ bf16  g_hlo[LAYERS*2*BH];
__device__ float g_gates[(size_t)LAYERS*6*BH];  // [l][pg] 64x1024 f32 planes
__device__ int   g_flag[LAYERS*8];              // per (layer, unit-block) monotonic

// ---------------- helpers ----------------------------------------------------
__device__ __forceinline__ void ldsm4(uint32_t r[4], const bf16* p) {
    uint32_t a = (uint32_t)__cvta_generic_to_shared(p);
    asm volatile("ldmatrix.sync.aligned.m8n8.x4.shared.b16 {%0,%1,%2,%3}, [%4];"
                 : "=r"(r[0]), "=r"(r[1]), "=r"(r[2]), "=r"(r[3]) : "r"(a));
}

__device__ __forceinline__ void mma16816(float c[4], const uint32_t a[4],
                                         uint32_t b0, uint32_t b1) {
    asm volatile("mma.sync.aligned.m16n8k16.row.col.f32.bf16.bf16.f32 "
                 "{%0,%1,%2,%3}, {%4,%5,%6,%7}, {%8,%9}, {%0,%1,%2,%3};"
                 : "+f"(c[0]), "+f"(c[1]), "+f"(c[2]), "+f"(c[3])
                 : "r"(a[0]), "r"(a[1]), "r"(a[2]), "r"(a[3]), "r"(b0), "r"(b1));
}

__device__ __forceinline__ void split2(float v, bf16& hi, bf16& lo) {
    hi = __float2bfloat16_rn(v);
    lo = __float2bfloat16_rn(v - __bfloat162float(hi));
}

__device__ __forceinline__ void cp16(bf16* dst, const bf16* src) {
    uint32_t d = (uint32_t)__cvta_generic_to_shared(dst);
    asm volatile("cp.async.cg.shared.global [%0], [%1], 16;" :: "r"(d), "l"(src));
}

// ---------------- prep kernels ----------------------------------------------
__global__ void permute_weights_kernel(const float* __restrict__ wih,
                                       const float* __restrict__ whh) {
    size_t i = (size_t)blockIdx.x * blockDim.x + threadIdx.x;
    if (i >= (size_t)LAYERS * 3 * HID * HID) return;
    int k = (int)(i % HID);
    size_t row = i / HID;
    int l = (int)(row / (3 * HID));
    int r = (int)(row % (3 * HID));
    int g = r >> 10, u = r & 1023;
    int ub = u >> 7, rr = u & 127;
    size_t dih = ((size_t)(((l * 2 + 0) * 3 + g) * 8 + ub)) * WBLK + (size_t)rr * 1024 + k;
    size_t dhh = ((size_t)(((l * 2 + 1) * 3 + g) * 8 + ub)) * WBLK + (size_t)rr * 1024 + k;
    bf16 hi, lo;
    split2(wih[i], hi, lo); g_wBhi[dih] = hi; g_wBlo[dih] = lo;
    split2(whh[i], hi, lo); g_wBhi[dhh] = hi; g_wBlo[dhh] = lo;
}

__global__ void split_x_kernel(const float* __restrict__ x) {
    size_t i = (size_t)blockIdx.x * blockDim.x + threadIdx.x;
    if (i >= (size_t)S_LEN * BH) return;
    bf16 hi, lo;
    split2(x[i], hi, lo); g_xhi[i] = hi; g_xlo[i] = lo;
}

__global__ void init_h_kernel(const float* __restrict__ h0) {
    size_t i = (size_t)blockIdx.x * blockDim.x + threadIdx.x;
    if (i < LAYERS * 8 && blockIdx.x == 0 && threadIdx.x < LAYERS * 8)
        g_flag[threadIdx.x] = 0;
    if (i >= (size_t)LAYERS * BH) return;
    int l = (int)(i / BH);
    size_t j = i % BH;
    float v = h0[i];
    size_t dst = ((size_t)l * 2 + 0) * BH + j;
    g_h[dst] = v;
    bf16 hi, lo;
    split2(v, hi, lo); g_hhi[dst] = hi; g_hlo[dst] = lo;
}

// ---------------- chunk loader -----------------------------------------------
__device__ __forceinline__ void load_chunk(
    bf16* slot, int kb,
    const bf16* __restrict__ Ahi, const bf16* __restrict__ Alo,   // 64 x 1024
    const bf16* __restrict__ Whi, const bf16* __restrict__ Wlo,   // 128 x 1024
    int tid)
{
    // A: 2 planes x 64 rows x 64 halfs (8 x 16B per row)
#pragma unroll
    for (int i = tid; i < 1024; i += 512) {
        int row = i >> 3, c16 = i & 7;
        int pl = row >> 6, r = row & 63;
        const bf16* src = (pl ? Alo : Ahi) + (size_t)r * 1024 + kb + c16 * 8;
        cp16(slot + row * SR + c16 * 8, src);
    }
    // W: 2 planes x 128 rows
#pragma unroll
    for (int i = tid; i < 2048; i += 512) {
        int row = i >> 3, c16 = i & 7;
        int pl = row >> 7, r = row & 127;
        const bf16* src = (pl ? Wlo : Whi) + (size_t)r * 1024 + kb + c16 * 8;
        cp16(slot + (128 + row) * SR + c16 * 8, src);
    }
}

// ---------------- fused GRU step ---------------------------------------------
// grid (48, 3): blockIdx.y = layer; q = blockIdx.x: p=q/24, g=(q%24)/8, ub=q%8.
// CTA GEMM: M=64 (batch), N=128 (units of one gate, one path), K=1024, bf16x3.
// Then 6-CTA group rendezvous per (layer, ub) and distributed pointwise GRU.
__global__ __launch_bounds__(512) void gru_step_kernel(
    int gs, const float* __restrict__ bih, const float* __restrict__ bhh,
    float* __restrict__ out)
{
    const int l = blockIdx.y;
    const int t = gs - l;
    if (t < 0 || t >= S_LEN) return;

    const int q  = blockIdx.x;
    const int p  = q / 24;              // 0: gi (x-path), 1: gh (h-path)
    const int g  = (q % 24) / 8;        // gate r/z/n
    const int ub = q & 7;               // unit block (128 units)
    const int u0 = ub * 128;

    const int tid  = threadIdx.x;
    const int lane = tid & 31;
    const int wid  = tid >> 5;
    const int wm   = wid >> 2;          // 0..3 -> batch rows 16*wm
    const int wn   = wid & 3;           // 0..3 -> unit cols 32*wn

    extern __shared__ __align__(16) unsigned char smem_raw[];
    uint32_t dyn_u = (uint32_t)__cvta_generic_to_shared(smem_raw);
    uint32_t s0u   = (dyn_u + 1023u) & ~1023u;
    bf16* sbase = (bf16*)(smem_raw + (s0u - dyn_u));

    const int par = t & 1;
    const bf16 *Ahi, *Alo;
    if (p == 0) {
        if (l == 0) { Ahi = g_xhi + (size_t)t * BH;  Alo = g_xlo + (size_t)t * BH; }
        else {
            size_t o = ((size_t)(l - 1) * 2 + (par ^ 1)) * BH;   // h_{l-1}[t]
            Ahi = g_hhi + o;  Alo = g_hlo + o;
        }
    } else {
        size_t o = ((size_t)l * 2 + par) * BH;                    // h_l[t-1]
        Ahi = g_hhi + o;  Alo = g_hlo + o;
    }
    size_t wb = (size_t)(((l * 2 + p) * 3 + g) * 8 + ub) * WBLK;
    const bf16* Whi = g_wBhi + wb;
    const bf16* Wlo = g_wBlo + wb;

    float acc[4][4];
#pragma unroll
    for (int j = 0; j < 4; ++j)
#pragma unroll
        for (int c = 0; c < 4; ++c) acc[j][c] = 0.f;

    const int rowA  = wm * 16 + (lane & 15);
    const int ahalf = (lane >> 4) * 8;
    const int rowB  = (lane & 7) + ((lane & 16) ? 8 : 0);
    const int bhalf = (lane & 8) ? 8 : 0;

    // ---- prologue: prefetch chunks 0,1 ----
#pragma unroll
    for (int c = 0; c < DEPTH - 1; ++c) {
        load_chunk(sbase + (size_t)c * SLOT_HALFS, c * KCH, Ahi, Alo, Whi, Wlo, tid);
        asm volatile("cp.async.commit_group;" ::: "memory");
    }

    // ---- main loop: 16 chunks, depth-3 ring ----
    for (int c = 0; c < CHUNKS; ++c) {
        asm volatile("cp.async.wait_group 1;" ::: "memory");
        __syncthreads();
        const int nc = c + DEPTH - 1;
        if (nc < CHUNKS)
            load_chunk(sbase + (size_t)(nc % DEPTH) * SLOT_HALFS, nc * KCH,
                       Ahi, Alo, Whi, Wlo, tid);
        asm volatile("cp.async.commit_group;" ::: "memory");   // drain-safe

        const bf16* slot = sbase + (size_t)(c % DEPTH) * SLOT_HALFS;
#pragma unroll
        for (int ks = 0; ks < 4; ++ks) {
            uint32_t ah[4], al[4];
            ldsm4(ah, slot + rowA * SR + ks * 16 + ahalf);
            ldsm4(al, slot + (64 + rowA) * SR + ks * 16 + ahalf);
#pragma unroll
            for (int np = 0; np < 2; ++np) {      // 16 W rows -> 2 n8 frags
                uint32_t bh[4], bl[4];
                int wr = 128 + wn * 32 + np * 16 + rowB;
                ldsm4(bh, slot + wr * SR + ks * 16 + bhalf);
                ldsm4(bl, slot + (wr + 128) * SR + ks * 16 + bhalf);
                int f = np * 2;
                // bf16x3: hi*hi + lo*hi + hi*lo
                mma16816(acc[f],     ah, bh[0], bh[1]);
                mma16816(acc[f],     al, bh[0], bh[1]);
                mma16816(acc[f],     ah, bl[0], bl[1]);
                mma16816(acc[f + 1], ah, bh[2], bh[3]);
                mma16816(acc[f + 1], al, bh[2], bh[3]);
                mma16816(acc[f + 1], ah, bl[2], bl[3]);
            }
        }
    }
    asm volatile("cp.async.wait_group 0;" ::: "memory");

    // ---- store gate tile to global f32 buffer ----
    {
        float* plane = g_gates + (size_t)(l * 6 + p * 3 + g) * BH;
        int gr = lane >> 2, t4 = lane & 3;
#pragma unroll
        for (int f = 0; f < 4; ++f) {
            int u = u0 + wn * 32 + f * 8 + t4 * 2;
            int r0 = wm * 16 + gr;
            *(float2*)(plane + (size_t)r0 * 1024 + u)       = make_float2(acc[f][0], acc[f][1]);
            *(float2*)(plane + (size_t)(r0 + 8) * 1024 + u) = make_float2(acc[f][2], acc[f][3]);
        }
    }

    // ---- group rendezvous: 6 CTAs of (l, ub) ----
    __syncthreads();
    if (tid == 0) {
        __threadfence();
        atomicAdd(&g_flag[l * 8 + ub], 1);
        const int target = 6 * (t + 1);
        volatile int* fp = &g_flag[l * 8 + ub];
        while (*fp < target) __nanosleep(64);
    }
    __syncthreads();
    __threadfence();

    // ---- distributed pointwise GRU: this CTA does slice (p*3+g) of 8192 ----
    const int lG = l * 3 * HID;
    const float* bihp = bih + lG;
    const float* bhhp = bhh + lG;
    const float* hsrc = g_h + ((size_t)l * 2 + par) * BH;
    float*       hdst = g_h + ((size_t)l * 2 + (par ^ 1)) * BH;
    bf16* hhid = g_hhi + ((size_t)l * 2 + (par ^ 1)) * BH;
    bf16* hlod = g_hlo + ((size_t)l * 2 + (par ^ 1)) * BH;
    const float* GI = g_gates + (size_t)(l * 6) * BH;        // pg 0..2 (gi r/z/n)
    const float* GH = g_gates + (size_t)(l * 6 + 3) * BH;    // pg 3..5 (gh r/z/n)

    const int sl    = p * 3 + g;
    const int start = sl * 1366;
    const int end   = (start + 1366 < 8192) ? start + 1366 : 8192;
    for (int e = start + tid; e < end; e += 512) {
        int b  = e >> 7;
        int u  = u0 + (e & 127);
        size_t ix = (size_t)b * 1024 + u;
        float gi_r = GI[ix],          gh_r = GH[ix];
        float gi_z = GI[BH + ix],     gh_z = GH[BH + ix];
        float gi_n = GI[2 * (size_t)BH + ix], gh_n = GH[2 * (size_t)BH + ix];
        float pr = gi_r + bihp[u]           + gh_r + bhhp[u];
        float pz = gi_z + bihp[HID + u]     + gh_z + bhhp[HID + u];
        float rg = 1.f / (1.f + __expf(-pr));
        float zg = 1.f / (1.f + __expf(-pz));
        float nn = tanhf(gi_n + bihp[2 * HID + u] + rg * (gh_n + bhhp[2 * HID + u]));
        float hold = hsrc[ix];
        float hn = (1.f - zg) * nn + zg * hold;
        hdst[ix] = hn;
        bf16 hi, lo;
        split2(hn, hi, lo);
        hhid[ix] = hi;
        hlod[ix] = lo;
        if (l == LAYERS - 1)
            out[(size_t)t * BH + ix] = hn;
    }
}

// ---------------- launch -----------------------------------------------------
extern "C" void kernel_launch(void* const* d_in, const int* in_sizes, int n_in,
                              void* d_out, int out_size)
{
    const float* x   = (const float*)d_in[0];
    const float* h0  = (const float*)d_in[1];
    const float* wih = (const float*)d_in[2];
    const float* whh = (const float*)d_in[3];
    const float* bih = (const float*)d_in[4];
    const float* bhh = (const float*)d_in[5];
    float* out = (float*)d_out;

    cudaFuncSetAttribute(gru_step_kernel,
                         cudaFuncAttributeMaxDynamicSharedMemorySize, SMEM_REQ);

    {
        size_t n = (size_t)LAYERS * 3 * HID * HID;
        permute_weights_kernel<<<(unsigned)((n + 255) / 256), 256>>>(wih, whh);
    }
    {
        size_t n = (size_t)S_LEN * BH;
        split_x_kernel<<<(unsigned)((n + 255) / 256), 256>>>(x);
    }
    {
        size_t n = (size_t)LAYERS * BH;
        init_h_kernel<<<(unsigned)((n + 255) / 256), 256>>>(h0);  // also resets flags
    }
    for (int gs = 0; gs < S_LEN + LAYERS - 1; ++gs)
        gru_step_kernel<<<dim3(48, 3), 512, SMEM_REQ>>>(gs, bih, bhh, out);
}

// round 8
// speedup vs baseline: 2.9772x; 1.0264x over previous
#include <cuda_runtime.h>
#include <cuda_bf16.h>
#include <cstdint>

#define S_LEN  512
#define BATCH  64
#define HID    1024
#define LAYERS 3
#define BH     (BATCH*HID)     // 65536
#define KCH    64              // K per chunk
#define CHUNKS 16              // 1024/64
#define DEPTH  3               // cp.async ring depth

#define SR     72              // smem row stride in halfs (144B)
// slot rows: [0,64) A_hi, [64,128) A_lo, [128,256) W_hi, [256,384) W_lo
#define SLOT_HALFS (384*SR)            // 27648
#define SLOT_BYTES (SLOT_HALFS*2)      // 55296
#define SMEM_REQ (1024 + DEPTH*SLOT_BYTES)   // 166912 B

#define WBLK   (128*1024)      // one weight block: 128 rows x K=1024

typedef __nv_bfloat16 bf16;

// ---------------- device scratch (no runtime allocation) -------------------
__device__ bf16 g_xhi[(size_t)S_LEN*BH];
__device__ bf16 g_xlo[(size_t)S_LEN*BH];
__device__ bf16 g_wBhi[(size_t)LAYERS*2*3*8*WBLK];
__device__ bf16 g_wBlo[(size_t)LAYERS*2*3*8*WBLK];
__device__ float g_h  [LAYERS*2*BH];            // h state, parity double buffer
__device__ bf16  g_hhi[LAYERS*2*BH];
__device__ bf16  g_hlo[LAYERS*2*BH];
__device__ float g_gates[(size_t)2*LAYERS*6*BH]; // parity-double-buffered
__device__ int   g_flag[LAYERS*8];               // group rendezvous (l,ub)
__device__ int   g_lflag[LAYERS];                // per-layer completed-CTA count

// ---------------- helpers ----------------------------------------------------
__device__ __forceinline__ void ldsm4(uint32_t r[4], const bf16* p) {
    uint32_t a = (uint32_t)__cvta_generic_to_shared(p);
    asm volatile("ldmatrix.sync.aligned.m8n8.x4.shared.b16 {%0,%1,%2,%3}, [%4];"
                 : "=r"(r[0]), "=r"(r[1]), "=r"(r[2]), "=r"(r[3]) : "r"(a));
}

__device__ __forceinline__ void mma16816(float c[4], const uint32_t a[4],
                                         uint32_t b0, uint32_t b1) {
    asm volatile("mma.sync.aligned.m16n8k16.row.col.f32.bf16.bf16.f32 "
                 "{%0,%1,%2,%3}, {%4,%5,%6,%7}, {%8,%9}, {%0,%1,%2,%3};"
                 : "+f"(c[0]), "+f"(c[1]), "+f"(c[2]), "+f"(c[3])
                 : "r"(a[0]), "r"(a[1]), "r"(a[2]), "r"(a[3]), "r"(b0), "r"(b1));
}

__device__ __forceinline__ void split2(float v, bf16& hi, bf16& lo) {
    hi = __float2bfloat16_rn(v);
    lo = __float2bfloat16_rn(v - __bfloat162float(hi));
}

__device__ __forceinline__ void cp16(bf16* dst, const bf16* src) {
    uint32_t d = (uint32_t)__cvta_generic_to_shared(dst);
    asm volatile("cp.async.cg.shared.global [%0], [%1], 16;" :: "r"(d), "l"(src));
}

__device__ __forceinline__ int ldacq(const int* p) {
    int v;
    asm volatile("ld.acquire.gpu.s32 %0, [%1];" : "=r"(v) : "l"(p) : "memory");
    return v;
}

__device__ __forceinline__ void spin_ge(const int* p, int target) {
    while (ldacq(p) < target) __nanosleep(64);
}

// ---------------- prep kernels ----------------------------------------------
__global__ void permute_weights_kernel(const float* __restrict__ wih,
                                       const float* __restrict__ whh) {
    size_t i = (size_t)blockIdx.x * blockDim.x + threadIdx.x;
    if (i >= (size_t)LAYERS * 3 * HID * HID) return;
    int k = (int)(i % HID);
    size_t row = i / HID;
    int l = (int)(row / (3 * HID));
    int r = (int)(row % (3 * HID));
    int g = r >> 10, u = r & 1023;
    int ub = u >> 7, rr = u & 127;
    size_t dih = ((size_t)(((l * 2 + 0) * 3 + g) * 8 + ub)) * WBLK + (size_t)rr * 1024 + k;
    size_t dhh = ((size_t)(((l * 2 + 1) * 3 + g) * 8 + ub)) * WBLK + (size_t)rr * 1024 + k;
    bf16 hi, lo;
    split2(wih[i], hi, lo); g_wBhi[dih] = hi; g_wBlo[dih] = lo;
    split2(whh[i], hi, lo); g_wBhi[dhh] = hi; g_wBlo[dhh] = lo;
}

__global__ void split_x_kernel(const float* __restrict__ x) {
    size_t i = (size_t)blockIdx.x * blockDim.x + threadIdx.x;
    if (i >= (size_t)S_LEN * BH) return;
    bf16 hi, lo;
    split2(x[i], hi, lo); g_xhi[i] = hi; g_xlo[i] = lo;
}

__global__ void init_h_kernel(const float* __restrict__ h0) {
    if (blockIdx.x == 0 && threadIdx.x < LAYERS * 8) {
        g_flag[threadIdx.x] = 0;
        if (threadIdx.x < LAYERS) g_lflag[threadIdx.x] = 0;
    }
    size_t i = (size_t)blockIdx.x * blockDim.x + threadIdx.x;
    if (i >= (size_t)LAYERS * BH) return;
    int l = (int)(i / BH);
    size_t j = i % BH;
    float v = h0[i];
    size_t dst = ((size_t)l * 2 + 0) * BH + j;
    g_h[dst] = v;
    bf16 hi, lo;
    split2(v, hi, lo); g_hhi[dst] = hi; g_hlo[dst] = lo;
}

// ---------------- chunk loaders ---------------------------------------------
__device__ __forceinline__ void load_chunk_A(
    bf16* slot, int kb,
    const bf16* __restrict__ Ahi, const bf16* __restrict__ Alo, int tid)
{
#pragma unroll
    for (int i = tid; i < 1024; i += 512) {
        int row = i >> 3, c16 = i & 7;
        int pl = row >> 6, r = row & 63;
        const bf16* src = (pl ? Alo : Ahi) + (size_t)r * 1024 + kb + c16 * 8;
        cp16(slot + row * SR + c16 * 8, src);
    }
}

__device__ __forceinline__ void load_chunk_W(
    bf16* slot, int kb,
    const bf16* __restrict__ Whi, const bf16* __restrict__ Wlo, int tid)
{
#pragma unroll
    for (int i = tid; i < 2048; i += 512) {
        int row = i >> 3, c16 = i & 7;
        int pl = row >> 7, r = row & 127;
        const bf16* src = (pl ? Wlo : Whi) + (size_t)r * 1024 + kb + c16 * 8;
        cp16(slot + (128 + row) * SR + c16 * 8, src);
    }
}

// ---------------- persistent GRU kernel --------------------------------------
// grid (48, 3): l = blockIdx.y; q: p=q/24, g=(q%24)/8, ub=q%8. Each CTA loops
// t = 0..511 in its fixed role, synchronized by acquire/release flags.
__global__ __launch_bounds__(512) void gru_persistent_kernel(
    const float* __restrict__ bih, const float* __restrict__ bhh,
    float* __restrict__ out)
{
    const int l  = blockIdx.y;
    const int q  = blockIdx.x;
    const int p  = q / 24;
    const int g  = (q % 24) / 8;
    const int ub = q & 7;
    const int u0 = ub * 128;

    const int tid  = threadIdx.x;
    const int lane = tid & 31;
    const int wid  = tid >> 5;
    const int wm   = wid >> 2;
    const int wn   = wid & 3;

    extern __shared__ __align__(16) unsigned char smem_raw[];
    uint32_t dyn_u = (uint32_t)__cvta_generic_to_shared(smem_raw);
    uint32_t s0u   = (dyn_u + 1023u) & ~1023u;
    bf16* sbase = (bf16*)(smem_raw + (s0u - dyn_u));

    size_t wb = (size_t)(((l * 2 + p) * 3 + g) * 8 + ub) * WBLK;
    const bf16* Whi = g_wBhi + wb;
    const bf16* Wlo = g_wBlo + wb;

    const int rowA  = wm * 16 + (lane & 15);
    const int ahalf = (lane >> 4) * 8;
    const int rowB  = (lane & 7) + ((lane & 16) ? 8 : 0);
    const int bhalf = (lane & 8) ? 8 : 0;

    const int lG = l * 3 * HID;
    const float* bihp = bih + lG;
    const float* bhhp = bhh + lG;
    const int sl    = p * 3 + g;
    const int start = sl * 1366;
    const int end   = (start + 1366 < 8192) ? start + 1366 : 8192;

    for (int t = 0; t < S_LEN; ++t) {
        const int par = t & 1;

        const bf16 *Ahi, *Alo;
        if (p == 0) {
            if (l == 0) { Ahi = g_xhi + (size_t)t * BH;  Alo = g_xlo + (size_t)t * BH; }
            else {
                size_t o = ((size_t)(l - 1) * 2 + (par ^ 1)) * BH;   // h_{l-1}[t]
                Ahi = g_hhi + o;  Alo = g_hlo + o;
            }
        } else {
            size_t o = ((size_t)l * 2 + par) * BH;                    // h_l[t-1]
            Ahi = g_hhi + o;  Alo = g_hlo + o;
        }

        float acc[4][4];
#pragma unroll
        for (int j = 0; j < 4; ++j)
#pragma unroll
            for (int c = 0; c < 4; ++c) acc[j][c] = 0.f;

        // ---- W of chunk 0 (no cross-step dependency) hides the flag spin ----
        load_chunk_W(sbase, 0, Whi, Wlo, tid);
        if (tid == 0) {
            spin_ge(&g_lflag[l], 48 * t);                       // own layer t-1 done
            if (p == 0 && l > 0) spin_ge(&g_lflag[l - 1], 48 * (t + 1));
            if (l < LAYERS - 1 && t >= 1) spin_ge(&g_lflag[l + 1], 48 * (t - 1));
        }
        __syncthreads();
        load_chunk_A(sbase, 0, Ahi, Alo, tid);
        asm volatile("cp.async.commit_group;" ::: "memory");
        load_chunk_W(sbase + SLOT_HALFS, KCH, Whi, Wlo, tid);
        load_chunk_A(sbase + SLOT_HALFS, KCH, Ahi, Alo, tid);
        asm volatile("cp.async.commit_group;" ::: "memory");

        // ---- main loop: 16 chunks, depth-3 ring ----
        for (int c = 0; c < CHUNKS; ++c) {
            asm volatile("cp.async.wait_group 1;" ::: "memory");
            __syncthreads();
            const int nc = c + DEPTH - 1;
            if (nc < CHUNKS) {
                bf16* nslot = sbase + (size_t)(nc % DEPTH) * SLOT_HALFS;
                load_chunk_W(nslot, nc * KCH, Whi, Wlo, tid);
                load_chunk_A(nslot, nc * KCH, Ahi, Alo, tid);
            }
            asm volatile("cp.async.commit_group;" ::: "memory");   // drain-safe

            const bf16* slot = sbase + (size_t)(c % DEPTH) * SLOT_HALFS;
#pragma unroll
            for (int ks = 0; ks < 4; ++ks) {
                uint32_t ah[4], al[4];
                ldsm4(ah, slot + rowA * SR + ks * 16 + ahalf);
                ldsm4(al, slot + (64 + rowA) * SR + ks * 16 + ahalf);
#pragma unroll
                for (int np = 0; np < 2; ++np) {
                    uint32_t bh[4], bl[4];
                    int wr = 128 + wn * 32 + np * 16 + rowB;
                    ldsm4(bh, slot + wr * SR + ks * 16 + bhalf);
                    ldsm4(bl, slot + (wr + 128) * SR + ks * 16 + bhalf);
                    int f = np * 2;
                    mma16816(acc[f],     ah, bh[0], bh[1]);
                    mma16816(acc[f],     al, bh[0], bh[1]);
                    mma16816(acc[f],     ah, bl[0], bl[1]);
                    mma16816(acc[f + 1], ah, bh[2], bh[3]);
                    mma16816(acc[f + 1], al, bh[2], bh[3]);
                    mma16816(acc[f + 1], ah, bl[2], bl[3]);
                }
            }
        }
        asm volatile("cp.async.wait_group 0;" ::: "memory");

        // ---- store gate tile to global (parity-double-buffered) ----
        float* plane = g_gates + ((size_t)par * LAYERS * 6 + l * 6 + sl) * BH;
        {
            int gr = lane >> 2, t4 = lane & 3;
#pragma unroll
            for (int f = 0; f < 4; ++f) {
                int u = u0 + wn * 32 + f * 8 + t4 * 2;
                int r0 = wm * 16 + gr;
                *(float2*)(plane + (size_t)r0 * 1024 + u)       = make_float2(acc[f][0], acc[f][1]);
                *(float2*)(plane + (size_t)(r0 + 8) * 1024 + u) = make_float2(acc[f][2], acc[f][3]);
            }
        }

        // ---- group rendezvous: 6 CTAs of (l, ub) ----
        __syncthreads();
        if (tid == 0) {
            __threadfence();
            atomicAdd(&g_flag[l * 8 + ub], 1);
            spin_ge(&g_flag[l * 8 + ub], 6 * (t + 1));
        }
        __syncthreads();

        // ---- distributed pointwise GRU (slice sl of this ub's 8192 elems) ----
        const float* hsrc = g_h + ((size_t)l * 2 + par) * BH;
        float*       hdst = g_h + ((size_t)l * 2 + (par ^ 1)) * BH;
        bf16* hhid = g_hhi + ((size_t)l * 2 + (par ^ 1)) * BH;
        bf16* hlod = g_hlo + ((size_t)l * 2 + (par ^ 1)) * BH;
        const float* GI = g_gates + ((size_t)par * LAYERS * 6 + l * 6) * BH;
        const float* GH = GI + 3 * (size_t)BH;

        for (int e = start + tid; e < end; e += 512) {
            int b  = e >> 7;
            int u  = u0 + (e & 127);
            size_t ix = (size_t)b * 1024 + u;
            float gi_r = __ldcg(GI + ix),                 gh_r = __ldcg(GH + ix);
            float gi_z = __ldcg(GI + BH + ix),            gh_z = __ldcg(GH + BH + ix);
            float gi_n = __ldcg(GI + 2 * (size_t)BH + ix), gh_n = __ldcg(GH + 2 * (size_t)BH + ix);
            float pr = gi_r + bihp[u]           + gh_r + bhhp[u];
            float pz = gi_z + bihp[HID + u]     + gh_z + bhhp[HID + u];
            float rg = 1.f / (1.f + __expf(-pr));
            float zg = 1.f / (1.f + __expf(-pz));
            float nn = tanhf(gi_n + bihp[2 * HID + u] + rg * (gh_n + bhhp[2 * HID + u]));
            float hold = hsrc[ix];
            float hn = (1.f - zg) * nn + zg * hold;
            hdst[ix] = hn;
            bf16 hi, lo;
            split2(hn, hi, lo);
            hhid[ix] = hi;
            hlod[ix] = lo;
            if (l == LAYERS - 1)
                out[(size_t)t * BH + ix] = hn;
        }

        // ---- release: this CTA completed step t ----
        __syncthreads();
        if (tid == 0) {
            __threadfence();
            atomicAdd(&g_lflag[l], 1);
        }
    }
}

// ---------------- launch -----------------------------------------------------
extern "C" void kernel_launch(void* const* d_in, const int* in_sizes, int n_in,
                              void* d_out, int out_size)
{
    const float* x   = (const float*)d_in[0];
    const float* h0  = (const float*)d_in[1];
    const float* wih = (const float*)d_in[2];
    const float* whh = (const float*)d_in[3];
    const float* bih = (const float*)d_in[4];
    const float* bhh = (const float*)d_in[5];
    float* out = (float*)d_out;

    cudaFuncSetAttribute(gru_persistent_kernel,
                         cudaFuncAttributeMaxDynamicSharedMemorySize, SMEM_REQ);

    {
        size_t n = (size_t)LAYERS * 3 * HID * HID;
        permute_weights_kernel<<<(unsigned)((n + 255) / 256), 256>>>(wih, whh);
    }
    {
        size_t n = (size_t)S_LEN * BH;
        split_x_kernel<<<(unsigned)((n + 255) / 256), 256>>>(x);
    }
    {
        size_t n = (size_t)LAYERS * BH;
        init_h_kernel<<<(unsigned)((n + 255) / 256), 256>>>(h0);  // + flag reset
    }
    gru_persistent_kernel<<<dim3(48, 3), 512, SMEM_REQ>>>(bih, bhh, out);
}

// round 9
// speedup vs baseline: 3.0736x; 1.0324x over previous
#include <cuda_runtime.h>
#include <cuda_fp16.h>
#include <cstdint>

#define S_LEN  512
#define BATCH  64
#define HID    1024
#define LAYERS 3
#define BH     (BATCH*HID)     // 65536
#define KCH    64              // K per chunk
#define CHUNKS 16              // 1024/64
#define DEPTH  3               // cp.async ring depth

#define SR     72              // smem row stride in halfs (144B)
// slot rows: [0,64) A_hi, [64,128) A_lo, [128,256) W_hi, [256,384) W_lo
#define SLOT_HALFS (384*SR)            // 27648
#define SLOT_BYTES (SLOT_HALFS*2)      // 55296
#define SMEM_REQ (1024 + DEPTH*SLOT_BYTES)   // 166912 B

#define WBLK   (128*1024)      // one weight block: 128 rows x K=1024
#define LO_SCALE    2048.f
#define INV_LOSCALE (1.f/2048.f)

typedef __half h16;

// ---------------- device scratch (no runtime allocation) -------------------
__device__ h16 g_xhi[(size_t)S_LEN*BH];
__device__ h16 g_xlo[(size_t)S_LEN*BH];
__device__ h16 g_wBhi[(size_t)LAYERS*2*3*8*WBLK];
__device__ h16 g_wBlo[(size_t)LAYERS*2*3*8*WBLK];
__device__ float g_h  [LAYERS*2*BH];            // h state, parity double buffer
__device__ h16   g_hhi[LAYERS*2*BH];
__device__ h16   g_hlo[LAYERS*2*BH];
__device__ float g_gates[(size_t)2*LAYERS*6*BH]; // parity-double-buffered
__device__ int   g_flag[LAYERS*8];               // group rendezvous (l,ub)
__device__ int   g_lflag[LAYERS];                // per-layer completed-CTA count

// ---------------- helpers ----------------------------------------------------
__device__ __forceinline__ void ldsm4(uint32_t r[4], const h16* p) {
    uint32_t a = (uint32_t)__cvta_generic_to_shared(p);
    asm volatile("ldmatrix.sync.aligned.m8n8.x4.shared.b16 {%0,%1,%2,%3}, [%4];"
                 : "=r"(r[0]), "=r"(r[1]), "=r"(r[2]), "=r"(r[3]) : "r"(a));
}

// main product: f16 inputs, f32 accumulate
__device__ __forceinline__ void mma_f32acc(float c[4], const uint32_t a[4],
                                           uint32_t b0, uint32_t b1) {
    asm volatile("mma.sync.aligned.m16n8k16.row.col.f32.f16.f16.f32 "
                 "{%0,%1,%2,%3}, {%4,%5,%6,%7}, {%8,%9}, {%0,%1,%2,%3};"
                 : "+f"(c[0]), "+f"(c[1]), "+f"(c[2]), "+f"(c[3])
                 : "r"(a[0]), "r"(a[1]), "r"(a[2]), "r"(a[3]), "r"(b0), "r"(b1));
}

// cross products: f16 inputs, f16 accumulate (2 regs = 4 packed halfs)
__device__ __forceinline__ void mma_f16acc(uint32_t c[2], const uint32_t a[4],
                                           uint32_t b0, uint32_t b1) {
    asm volatile("mma.sync.aligned.m16n8k16.row.col.f16.f16.f16.f16 "
                 "{%0,%1}, {%2,%3,%4,%5}, {%6,%7}, {%0,%1};"
                 : "+r"(c[0]), "+r"(c[1])
                 : "r"(a[0]), "r"(a[1]), "r"(a[2]), "r"(a[3]), "r"(b0), "r"(b1));
}

// f16 digit split: hi = f16(v); lo = f16((v - hi) * 2048)
__device__ __forceinline__ void split2(float v, h16& hi, h16& lo) {
    hi = __float2half_rn(v);
    lo = __float2half_rn((v - __half2float(hi)) * LO_SCALE);
}

__device__ __forceinline__ void cp16(h16* dst, const h16* src) {
    uint32_t d = (uint32_t)__cvta_generic_to_shared(dst);
    asm volatile("cp.async.cg.shared.global [%0], [%1], 16;" :: "r"(d), "l"(src));
}

__device__ __forceinline__ int ldacq(const int* p) {
    int v;
    asm volatile("ld.acquire.gpu.s32 %0, [%1];" : "=r"(v) : "l"(p) : "memory");
    return v;
}

__device__ __forceinline__ void spin_ge(const int* p, int target) {
    while (ldacq(p) < target) __nanosleep(64);
}

// ---------------- prep kernels ----------------------------------------------
__global__ void permute_weights_kernel(const float* __restrict__ wih,
                                       const float* __restrict__ whh) {
    size_t i = (size_t)blockIdx.x * blockDim.x + threadIdx.x;
    if (i >= (size_t)LAYERS * 3 * HID * HID) return;
    int k = (int)(i % HID);
    size_t row = i / HID;
    int l = (int)(row / (3 * HID));
    int r = (int)(row % (3 * HID));
    int g = r >> 10, u = r & 1023;
    int ub = u >> 7, rr = u & 127;
    size_t dih = ((size_t)(((l * 2 + 0) * 3 + g) * 8 + ub)) * WBLK + (size_t)rr * 1024 + k;
    size_t dhh = ((size_t)(((l * 2 + 1) * 3 + g) * 8 + ub)) * WBLK + (size_t)rr * 1024 + k;
    h16 hi, lo;
    split2(wih[i], hi, lo); g_wBhi[dih] = hi; g_wBlo[dih] = lo;
    split2(whh[i], hi, lo); g_wBhi[dhh] = hi; g_wBlo[dhh] = lo;
}

__global__ void split_x_kernel(const float* __restrict__ x) {
    size_t i = (size_t)blockIdx.x * blockDim.x + threadIdx.x;
    if (i >= (size_t)S_LEN * BH) return;
    h16 hi, lo;
    split2(x[i], hi, lo); g_xhi[i] = hi; g_xlo[i] = lo;
}

__global__ void init_h_kernel(const float* __restrict__ h0) {
    if (blockIdx.x == 0 && threadIdx.x < LAYERS * 8) {
        g_flag[threadIdx.x] = 0;
        if (threadIdx.x < LAYERS) g_lflag[threadIdx.x] = 0;
    }
    size_t i = (size_t)blockIdx.x * blockDim.x + threadIdx.x;
    if (i >= (size_t)LAYERS * BH) return;
    int l = (int)(i / BH);
    size_t j = i % BH;
    float v = h0[i];
    size_t dst = ((size_t)l * 2 + 0) * BH + j;
    g_h[dst] = v;
    h16 hi, lo;
    split2(v, hi, lo); g_hhi[dst] = hi; g_hlo[dst] = lo;
}

// ---------------- chunk loaders ---------------------------------------------
__device__ __forceinline__ void load_chunk_A(
    h16* slot, int kb,
    const h16* __restrict__ Ahi, const h16* __restrict__ Alo, int tid)
{
#pragma unroll
    for (int i = tid; i < 1024; i += 512) {
        int row = i >> 3, c16 = i & 7;
        int pl = row >> 6, r = row & 63;
        const h16* src = (pl ? Alo : Ahi) + (size_t)r * 1024 + kb + c16 * 8;
        cp16(slot + row * SR + c16 * 8, src);
    }
}

__device__ __forceinline__ void load_chunk_W(
    h16* slot, int kb,
    const h16* __restrict__ Whi, const h16* __restrict__ Wlo, int tid)
{
#pragma unroll
    for (int i = tid; i < 2048; i += 512) {
        int row = i >> 3, c16 = i & 7;
        int pl = row >> 7, r = row & 127;
        const h16* src = (pl ? Wlo : Whi) + (size_t)r * 1024 + kb + c16 * 8;
        cp16(slot + (128 + row) * SR + c16 * 8, src);
    }
}

// ---------------- persistent GRU kernel --------------------------------------
// grid (48, 3): l = blockIdx.y; q: p=q/24, g=(q%24)/8, ub=q%8. Each CTA loops
// t = 0..511 in its fixed role, synchronized by acquire/release flags.
__global__ __launch_bounds__(512) void gru_persistent_kernel(
    const float* __restrict__ bih, const float* __restrict__ bhh,
    float* __restrict__ out)
{
    const int l  = blockIdx.y;
    const int q  = blockIdx.x;
    const int p  = q / 24;
    const int g  = (q % 24) / 8;
    const int ub = q & 7;
    const int u0 = ub * 128;

    const int tid  = threadIdx.x;
    const int lane = tid & 31;
    const int wid  = tid >> 5;
    const int wm   = wid >> 2;
    const int wn   = wid & 3;

    extern __shared__ __align__(16) unsigned char smem_raw[];
    uint32_t dyn_u = (uint32_t)__cvta_generic_to_shared(smem_raw);
    uint32_t s0u   = (dyn_u + 1023u) & ~1023u;
    h16* sbase = (h16*)(smem_raw + (s0u - dyn_u));

    size_t wb = (size_t)(((l * 2 + p) * 3 + g) * 8 + ub) * WBLK;
    const h16* Whi = g_wBhi + wb;
    const h16* Wlo = g_wBlo + wb;

    const int rowA  = wm * 16 + (lane & 15);
    const int ahalf = (lane >> 4) * 8;
    const int rowB  = (lane & 7) + ((lane & 16) ? 8 : 0);
    const int bhalf = (lane & 8) ? 8 : 0;

    const int lG = l * 3 * HID;
    const float* bihp = bih + lG;
    const float* bhhp = bhh + lG;
    const int sl    = p * 3 + g;
    const int start = sl * 1366;
    const int end   = (start + 1366 < 8192) ? start + 1366 : 8192;

    for (int t = 0; t < S_LEN; ++t) {
        const int par = t & 1;

        const h16 *Ahi, *Alo;
        if (p == 0) {
            if (l == 0) { Ahi = g_xhi + (size_t)t * BH;  Alo = g_xlo + (size_t)t * BH; }
            else {
                size_t o = ((size_t)(l - 1) * 2 + (par ^ 1)) * BH;   // h_{l-1}[t]
                Ahi = g_hhi + o;  Alo = g_hlo + o;
            }
        } else {
            size_t o = ((size_t)l * 2 + par) * BH;                    // h_l[t-1]
            Ahi = g_hhi + o;  Alo = g_hlo + o;
        }

        float acc[4][4];          // main product, f32
        uint32_t cacc[4][2];      // cross products, packed f16 (scaled by 2048)
#pragma unroll
        for (int j = 0; j < 4; ++j) {
#pragma unroll
            for (int c = 0; c < 4; ++c) acc[j][c] = 0.f;
            cacc[j][0] = 0u; cacc[j][1] = 0u;
        }

        // ---- W of chunk 0 (no cross-step dependency) hides the flag spin ----
        load_chunk_W(sbase, 0, Whi, Wlo, tid);
        if (tid == 0) {
            spin_ge(&g_lflag[l], 48 * t);                       // own layer t-1 done
            if (p == 0 && l > 0) spin_ge(&g_lflag[l - 1], 48 * (t + 1));
            if (l < LAYERS - 1 && t >= 1) spin_ge(&g_lflag[l + 1], 48 * (t - 1));
        }
        __syncthreads();
        load_chunk_A(sbase, 0, Ahi, Alo, tid);
        asm volatile("cp.async.commit_group;" ::: "memory");
        load_chunk_W(sbase + SLOT_HALFS, KCH, Whi, Wlo, tid);
        load_chunk_A(sbase + SLOT_HALFS, KCH, Ahi, Alo, tid);
        asm volatile("cp.async.commit_group;" ::: "memory");

        // ---- main loop: 16 chunks, depth-3 ring ----
        for (int c = 0; c < CHUNKS; ++c) {
            asm volatile("cp.async.wait_group 1;" ::: "memory");
            __syncthreads();
            const int nc = c + DEPTH - 1;
            if (nc < CHUNKS) {
                h16* nslot = sbase + (size_t)(nc % DEPTH) * SLOT_HALFS;
                load_chunk_W(nslot, nc * KCH, Whi, Wlo, tid);
                load_chunk_A(nslot, nc * KCH, Ahi, Alo, tid);
            }
            asm volatile("cp.async.commit_group;" ::: "memory");   // drain-safe

            const h16* slot = sbase + (size_t)(c % DEPTH) * SLOT_HALFS;
#pragma unroll
            for (int ks = 0; ks < 4; ++ks) {
                uint32_t ah[4], al[4];
                ldsm4(ah, slot + rowA * SR + ks * 16 + ahalf);
                ldsm4(al, slot + (64 + rowA) * SR + ks * 16 + ahalf);
#pragma unroll
                for (int np = 0; np < 2; ++np) {
                    uint32_t bh[4], bl[4];
                    int wr = 128 + wn * 32 + np * 16 + rowB;
                    ldsm4(bh, slot + wr * SR + ks * 16 + bhalf);
                    ldsm4(bl, slot + (wr + 128) * SR + ks * 16 + bhalf);
                    int f = np * 2;
                    // main: hi*hi in f32 acc
                    mma_f32acc(acc[f],     ah, bh[0], bh[1]);
                    mma_f32acc(acc[f + 1], ah, bh[2], bh[3]);
                    // cross: lo*hi + hi*lo, shared f16 acc (scaled x2048)
                    mma_f16acc(cacc[f],     al, bh[0], bh[1]);
                    mma_f16acc(cacc[f + 1], al, bh[2], bh[3]);
                    mma_f16acc(cacc[f],     ah, bl[0], bl[1]);
                    mma_f16acc(cacc[f + 1], ah, bl[2], bl[3]);
                }
            }
        }
        asm volatile("cp.async.wait_group 0;" ::: "memory");

        // ---- fold cross terms into main acc ----
#pragma unroll
        for (int f = 0; f < 4; ++f) {
            float2 c0 = __half22float2(*(const __half2*)&cacc[f][0]);
            float2 c1 = __half22float2(*(const __half2*)&cacc[f][1]);
            acc[f][0] += c0.x * INV_LOSCALE;
            acc[f][1] += c0.y * INV_LOSCALE;
            acc[f][2] += c1.x * INV_LOSCALE;
            acc[f][3] += c1.y * INV_LOSCALE;
        }

        // ---- store gate tile to global (parity-double-buffered) ----
        float* plane = g_gates + ((size_t)par * LAYERS * 6 + l * 6 + sl) * BH;
        {
            int gr = lane >> 2, t4 = lane & 3;
#pragma unroll
            for (int f = 0; f < 4; ++f) {
                int u = u0 + wn * 32 + f * 8 + t4 * 2;
                int r0 = wm * 16 + gr;
                *(float2*)(plane + (size_t)r0 * 1024 + u)       = make_float2(acc[f][0], acc[f][1]);
                *(float2*)(plane + (size_t)(r0 + 8) * 1024 + u) = make_float2(acc[f][2], acc[f][3]);
            }
        }

        // ---- group rendezvous: 6 CTAs of (l, ub) ----
        __syncthreads();
        if (tid == 0) {
            __threadfence();
            atomicAdd(&g_flag[l * 8 + ub], 1);
            spin_ge(&g_flag[l * 8 + ub], 6 * (t + 1));
        }
        __syncthreads();

        // ---- distributed pointwise GRU (slice sl of this ub's 8192 elems) ----
        const float* hsrc = g_h + ((size_t)l * 2 + par) * BH;
        float*       hdst = g_h + ((size_t)l * 2 + (par ^ 1)) * BH;
        h16* hhid = g_hhi + ((size_t)l * 2 + (par ^ 1)) * BH;
        h16* hlod = g_hlo + ((size_t)l * 2 + (par ^ 1)) * BH;
        const float* GI = g_gates + ((size_t)par * LAYERS * 6 + l * 6) * BH;
        const float* GH = GI + 3 * (size_t)BH;

        for (int e = start + tid; e < end; e += 512) {
            int b  = e >> 7;
            int u  = u0 + (e & 127);
            size_t ix = (size_t)b * 1024 + u;
            float gi_r = __ldcg(GI + ix),                  gh_r = __ldcg(GH + ix);
            float gi_z = __ldcg(GI + BH + ix),             gh_z = __ldcg(GH + BH + ix);
            float gi_n = __ldcg(GI + 2 * (size_t)BH + ix), gh_n = __ldcg(GH + 2 * (size_t)BH + ix);
            float pr = gi_r + bihp[u]           + gh_r + bhhp[u];
            float pz = gi_z + bihp[HID + u]     + gh_z + bhhp[HID + u];
            float rg = 1.f / (1.f + __expf(-pr));
            float zg = 1.f / (1.f + __expf(-pz));
            float nn = tanhf(gi_n + bihp[2 * HID + u] + rg * (gh_n + bhhp[2 * HID + u]));
            float hold = hsrc[ix];
            float hn = (1.f - zg) * nn + zg * hold;
            hdst[ix] = hn;
            h16 hi, lo;
            split2(hn, hi, lo);
            hhid[ix] = hi;
            hlod[ix] = lo;
            if (l == LAYERS - 1)
                out[(size_t)t * BH + ix] = hn;
        }

        // ---- release: this CTA completed step t ----
        __syncthreads();
        if (tid == 0) {
            __threadfence();
            atomicAdd(&g_lflag[l], 1);
        }
    }
}

// ---------------- launch -----------------------------------------------------
extern "C" void kernel_launch(void* const* d_in, const int* in_sizes, int n_in,
                              void* d_out, int out_size)
{
    const float* x   = (const float*)d_in[0];
    const float* h0  = (const float*)d_in[1];
    const float* wih = (const float*)d_in[2];
    const float* whh = (const float*)d_in[3];
    const float* bih = (const float*)d_in[4];
    const float* bhh = (const float*)d_in[5];
    float* out = (float*)d_out;

    cudaFuncSetAttribute(gru_persistent_kernel,
                         cudaFuncAttributeMaxDynamicSharedMemorySize, SMEM_REQ);

    {
        size_t n = (size_t)LAYERS * 3 * HID * HID;
        permute_weights_kernel<<<(unsigned)((n + 255) / 256), 256>>>(wih, whh);
    }
    {
        size_t n = (size_t)S_LEN * BH;
        split_x_kernel<<<(unsigned)((n + 255) / 256), 256>>>(x);
    }
    {
        size_t n = (size_t)LAYERS * BH;
        init_h_kernel<<<(unsigned)((n + 255) / 256), 256>>>(h0);  // + flag reset
    }
    gru_persistent_kernel<<<dim3(48, 3), 512, SMEM_REQ>>>(bih, bhh, out);
}